// round 2
// baseline (speedup 1.0000x reference)
#include <cuda_runtime.h>
#include <cstddef>

// Problem constants (Attention_88811333746876)
#define BB   32
#define HSZ  512
#define CC   256
#define HWN  4096     // 64*64
#define AA   256

#define PX   64       // pixels per fused block
#define NBLK (HWN / PX)   // 64 blocks per batch
#define TSTR 68       // tile row stride in floats (68 = 4 mod 32 -> conflict-free LDS.128)

// Scratch (allocation-free rule: __device__ globals)
__device__ float g_wh[BB * AA];              // 32 KB
__device__ float g_v [BB * CC];              // 32 KB
__device__ float g_pctx[BB * NBLK * CC];     // 2 MB partial contexts
__device__ float g_pm[BB * NBLK];            // per-block local max
__device__ float g_ps[BB * NBLK];            // per-block local exp-sum

// ---------------------------------------------------------------------------
// Kernel 1: wh[b,a] = sum_k h_dec[b,k] * W_h[k,a] + b_h[a]
// ---------------------------------------------------------------------------
__global__ void k_wh(const float* __restrict__ h_dec,
                     const float* __restrict__ W_h,
                     const float* __restrict__ b_h)
{
    const int b  = blockIdx.x;
    const int a0 = blockIdx.y * 64;
    const int t  = threadIdx.x;
    const int kpart = t >> 6;        // 0..3
    const int al    = t & 63;
    const int a     = a0 + al;

    const float* hd = h_dec + b * HSZ;
    const int k0 = kpart * (HSZ / 4);

    float acc = 0.f;
#pragma unroll 8
    for (int k = k0; k < k0 + HSZ / 4; ++k)
        acc += hd[k] * W_h[k * AA + a];

    __shared__ float part[4][64];
    part[kpart][al] = acc;
    __syncthreads();
    if (t < 64) {
        float s = part[0][t] + part[1][t] + part[2][t] + part[3][t] + b_h[a0 + t];
        g_wh[b * AA + a0 + t] = s;
    }
}

// ---------------------------------------------------------------------------
// Kernel 2: v[b,c] = sum_a W_fm[c,a] * wh[b,a]
// (b_fm dropped: constant shift per batch -> softmax invariant)
// ---------------------------------------------------------------------------
__global__ void k_v(const float* __restrict__ W_fm)
{
    const int b    = blockIdx.x;
    const int c    = blockIdx.y * 8 + (threadIdx.x >> 5);
    const int lane = threadIdx.x & 31;

    __shared__ float wh_s[AA];
    if (threadIdx.x < AA) wh_s[threadIdx.x] = g_wh[b * AA + threadIdx.x];
    __syncthreads();

    const float4* wrow = reinterpret_cast<const float4*>(W_fm + c * AA);
    const float4* whs4 = reinterpret_cast<const float4*>(wh_s);

    float acc = 0.f;
#pragma unroll
    for (int i = 0; i < 2; ++i) {
        const int idx = lane + i * 32;
        float4 wv = wrow[idx];
        float4 hv = whs4[idx];
        acc += wv.x * hv.x + wv.y * hv.y + wv.z * hv.z + wv.w * hv.w;
    }
#pragma unroll
    for (int o = 16; o; o >>= 1) acc += __shfl_xor_sync(0xffffffffu, acc, o);
    if (lane == 0) g_v[b * CC + c] = acc;
}

// ---------------------------------------------------------------------------
// Kernel 3 (fused): per (b, pixel-chunk) block:
//   load fm tile [CC x PX] to smem ONCE, then compute scores, local softmax
//   stats, and partial context sums -- fm touches HBM exactly once.
// ---------------------------------------------------------------------------
extern __shared__ float s_tile[];   // CC * TSTR floats = 69.6 KB

__global__ void __launch_bounds__(256, 3) k_fuse(const float* __restrict__ fm)
{
    const int b   = blockIdx.x;
    const int blk = blockIdx.y;           // 0..NBLK-1
    const int px0 = blk * PX;
    const int t   = threadIdx.x;          // 256

    __shared__ float v_s[CC];
    __shared__ float sp[256];
    __shared__ float s_arr[PX];
    __shared__ float e_sh[PX];
    __shared__ float m_sh, sum_sh;

    v_s[t] = g_v[b * CC + t];

    // ---- load tile: 4096 float4s, 16 per thread, coalesced ----
    const float4* fm4 = reinterpret_cast<const float4*>(fm + (size_t)b * CC * HWN);
    const int p40 = px0 >> 2;             // float4 col base within image row
#pragma unroll
    for (int i = 0; i < 16; ++i) {
        const int q  = t + i * 256;       // 0..4095
        const int c  = q >> 4;            // 16 float4 per c-row
        const int pj = q & 15;
        float4 f = fm4[c * (HWN / 4) + p40 + pj];
        float4* dst = reinterpret_cast<float4*>(&s_tile[c * TSTR + pj * 4]);
        *dst = f;                         // (c*TSTR + 4*pj) % 4 == 0 -> aligned
    }
    __syncthreads();

    // ---- scores: s[p] = sum_c tile[c][p] * v[c], 4-way c-split ----
    {
        const int p = t & 63;
        const int h = t >> 6;             // 0..3
        const int c0 = h * 64;
        float part = 0.f;
#pragma unroll 8
        for (int c = c0; c < c0 + 64; ++c)
            part += s_tile[c * TSTR + p] * v_s[c];
        sp[t] = part;
    }
    __syncthreads();
    if (t < PX)
        s_arr[t] = sp[t] + sp[t + 64] + sp[t + 128] + sp[t + 192];
    __syncthreads();

    // ---- local max over 64 scores ----
    if (t < 32) {
        float m = fmaxf(s_arr[t], s_arr[t + 32]);
#pragma unroll
        for (int o = 16; o; o >>= 1) m = fmaxf(m, __shfl_xor_sync(0xffffffffu, m, o));
        if (t == 0) m_sh = m;
    }
    __syncthreads();
    const float M = m_sh;

    if (t < PX) e_sh[t] = expf(s_arr[t] - M);
    __syncthreads();

    if (t < 32) {
        float s = e_sh[t] + e_sh[t + 32];
#pragma unroll
        for (int o = 16; o; o >>= 1) s += __shfl_xor_sync(0xffffffffu, s, o);
        if (t == 0) sum_sh = s;
    }
    __syncthreads();

    if (t == 0) {
        g_pm[b * NBLK + blk] = M;
        g_ps[b * NBLK + blk] = sum_sh;
    }

    // ---- partial ctx: pctx[c] = sum_p tile[c][p] * e[p], thread t = c ----
    {
        const float4* e4  = reinterpret_cast<const float4*>(e_sh);
        float acc = 0.f;
#pragma unroll
        for (int j = 0; j < 16; ++j) {
            float4 f = *reinterpret_cast<const float4*>(&s_tile[t * TSTR + j * 4]);
            float4 e = e4[j];
            acc += f.x * e.x + f.y * e.y + f.z * e.z + f.w * e.w;
        }
        g_pctx[((size_t)(b * NBLK + blk)) * CC + t] = acc;
    }
}

// ---------------------------------------------------------------------------
// Kernel 4: combine partials with exact softmax rescaling.
//   M = max_blk m ; denom = sum_blk s_blk*e^{m-M}
//   out[b,c] = (sum_blk pctx[blk][c]*e^{m_blk-M}) / denom
// ---------------------------------------------------------------------------
__global__ void k_combine(float* __restrict__ out)
{
    const int b = blockIdx.x;
    const int t = threadIdx.x;            // 256

    __shared__ float m_s[NBLK];
    __shared__ float w_s[NBLK];
    __shared__ float M_sh, denom_sh;

    if (t < NBLK) m_s[t] = g_pm[b * NBLK + t];
    __syncthreads();

    if (t < 32) {
        float m = fmaxf(m_s[t], m_s[t + 32]);
#pragma unroll
        for (int o = 16; o; o >>= 1) m = fmaxf(m, __shfl_xor_sync(0xffffffffu, m, o));
        if (t == 0) M_sh = m;
    }
    __syncthreads();
    const float M = M_sh;

    if (t < NBLK) w_s[t] = expf(m_s[t] - M);
    __syncthreads();

    if (t < 32) {
        float d = g_ps[b * NBLK + t]       * w_s[t]
                + g_ps[b * NBLK + t + 32]  * w_s[t + 32];
#pragma unroll
        for (int o = 16; o; o >>= 1) d += __shfl_xor_sync(0xffffffffu, d, o);
        if (t == 0) denom_sh = d;
    }
    __syncthreads();
    const float inv = 1.f / denom_sh;

    // thread t = channel c; coalesced across c
    float acc = 0.f;
#pragma unroll 8
    for (int blk = 0; blk < NBLK; ++blk)
        acc += g_pctx[((size_t)(b * NBLK + blk)) * CC + t] * w_s[blk];

    out[b * CC + t] = acc * inv;
}

// ---------------------------------------------------------------------------
// Launch
// ---------------------------------------------------------------------------
extern "C" void kernel_launch(void* const* d_in, const int* in_sizes, int n_in,
                              void* d_out, int out_size)
{
    const float* h_dec = nullptr;
    const float* fm    = nullptr;
    const float* W_fm  = nullptr;
    const float* W_h   = nullptr;
    const float* b_h   = nullptr;
    const float* biases[2] = {nullptr, nullptr};
    int nb = 0;

    for (int i = 0; i < n_in; ++i) {
        switch (in_sizes[i]) {
            case BB * HSZ:      h_dec = (const float*)d_in[i]; break;   // 16384
            case BB * CC * HWN: fm    = (const float*)d_in[i]; break;   // 33554432
            case CC * AA:       W_fm  = (const float*)d_in[i]; break;   // 65536
            case HSZ * AA:      W_h   = (const float*)d_in[i]; break;   // 131072
            case AA:            if (nb < 2) biases[nb++] = (const float*)d_in[i]; break;
            default: break;
        }
    }
    b_h = biases[1];   // metadata order: b_fm first, b_h second (b_fm unused)

    float* out = (float*)d_out;

    const int smem_bytes = CC * TSTR * sizeof(float);   // 69632
    static bool attr_set = false;
    if (!attr_set) {
        cudaFuncSetAttribute(k_fuse, cudaFuncAttributeMaxDynamicSharedMemorySize,
                             smem_bytes);
        attr_set = true;
    }

    k_wh     <<<dim3(BB, AA / 64), 256>>>(h_dec, W_h, b_h);
    k_v      <<<dim3(BB, CC / 8),  256>>>(W_fm);
    k_fuse   <<<dim3(BB, NBLK), 256, smem_bytes>>>(fm);
    k_combine<<<BB, 256>>>(out);
}

// round 4
// speedup vs baseline: 1.2159x; 1.2159x over previous
#include <cuda_runtime.h>
#include <cstddef>

// Problem constants (Attention_88811333746876)
#define BB   32
#define HSZ  512
#define CC   256
#define HWN  4096     // 64*64
#define AA   256

#define PX   64           // pixels per fused block
#define NBLK (HWN / PX)   // 64 blocks per batch

// Scratch (allocation-free rule: __device__ globals)
__device__ float g_whp[8 * BB * AA];         // k-split partials of wh (256 KB)
__device__ float g_v  [BB * CC];             // 32 KB
__device__ float g_pctx[BB * NBLK * CC];     // 2 MB partial contexts
__device__ float g_pm[BB * NBLK];            // per-block local max
__device__ float g_ps[BB * NBLK];            // per-block local exp-sum

// ---------------------------------------------------------------------------
// Kernel 1: wh partials. grid (4 a-tiles, 8 k-tiles), 256 thr.
// W_h is read exactly ONCE (512 KB total, coalesced float4).
// Block (ap,kp): partial wh[b, a0:a0+64] over k in [k0,k0+64) for ALL b.
// ---------------------------------------------------------------------------
__global__ void k_wh(const float* __restrict__ h_dec,
                     const float* __restrict__ W_h)
{
    __shared__ float Wt[64 * 64];   // [k][a] 16 KB
    __shared__ float hs[BB * 64];   // [b][k]  8 KB

    const int a0 = blockIdx.x * 64;
    const int k0 = blockIdx.y * 64;
    const int kp = blockIdx.y;
    const int t  = threadIdx.x;

    // load W_h tile: 64 k-rows x 16 float4 (64 a)
    {
        const float4* W4 = reinterpret_cast<const float4*>(W_h);
        const int a4 = t & 15, kk = t >> 4;
#pragma unroll
        for (int ii = 0; ii < 4; ++ii) {
            const int k = kk + ii * 16;
            float4 w = W4[(size_t)(k0 + k) * (AA / 4) + (a0 >> 2) + a4];
            reinterpret_cast<float4*>(Wt)[k * 16 + a4] = w;
        }
    }
    // load h_dec tile: 32 b x 64 k
    {
        const int k = t & 63, bq = t >> 6;
#pragma unroll
        for (int jj = 0; jj < 8; ++jj) {
            const int b = bq + jj * 4;
            hs[b * 64 + k] = h_dec[b * HSZ + k0 + k];
        }
    }
    __syncthreads();

    // compute: warp = 4 consecutive b (broadcast hs), lanes = a (stride-1 Wt)
    const int ap2 = t & 31;    // a = a0+ap2 and a0+ap2+32
    const int bq  = t >> 5;    // warp id -> b = bq*4 .. bq*4+3
    float acc[4][2] = {};
#pragma unroll 4
    for (int k = 0; k < 64; ++k) {
        const float w0 = Wt[k * 64 + ap2];
        const float w1 = Wt[k * 64 + ap2 + 32];
#pragma unroll
        for (int i = 0; i < 4; ++i) {
            const float h = hs[(bq * 4 + i) * 64 + k];
            acc[i][0] += h * w0;
            acc[i][1] += h * w1;
        }
    }
#pragma unroll
    for (int i = 0; i < 4; ++i) {
        const int b = bq * 4 + i;
        g_whp[(kp * BB + b) * AA + a0 + ap2]      = acc[i][0];
        g_whp[(kp * BB + b) * AA + a0 + ap2 + 32] = acc[i][1];
    }
}

// ---------------------------------------------------------------------------
// Kernel 2: v[b,c] = sum_a W_fm[c,a] * wh[b,a];  wh = sum of 8 k-partials + b_h.
// (b_fm dropped: it shifts scores by a per-b constant -> softmax invariant)
// ---------------------------------------------------------------------------
__global__ void k_v(const float* __restrict__ W_fm,
                    const float* __restrict__ b_h)
{
    const int b    = blockIdx.x;
    const int c    = blockIdx.y * 8 + (threadIdx.x >> 5);
    const int lane = threadIdx.x & 31;

    __shared__ float wh_s[AA];
    if (threadIdx.x < AA) {
        float s = b_h[threadIdx.x];
#pragma unroll
        for (int kp = 0; kp < 8; ++kp)
            s += g_whp[(kp * BB + b) * AA + threadIdx.x];
        wh_s[threadIdx.x] = s;
    }
    __syncthreads();

    const float4* wrow = reinterpret_cast<const float4*>(W_fm + c * AA);
    const float4* whs4 = reinterpret_cast<const float4*>(wh_s);

    float acc = 0.f;
#pragma unroll
    for (int i = 0; i < 2; ++i) {
        const int idx = lane + i * 32;
        float4 wv = wrow[idx];
        float4 hv = whs4[idx];
        acc += wv.x * hv.x + wv.y * hv.y + wv.z * hv.z + wv.w * hv.w;
    }
#pragma unroll
    for (int o = 16; o; o >>= 1) acc += __shfl_xor_sync(0xffffffffu, acc, o);
    if (lane == 0) g_v[b * CC + c] = acc;
}

// ---------------------------------------------------------------------------
// Kernel 3 (fused): per (b, 64-pixel chunk):
//   - stream fm tile [256c x 64px] from HBM ONCE; score partials computed
//     from registers DURING the load (no SMEM re-read for scores)
//   - tile stored to SMEM with XOR swizzle (64 KB, conflict-free STS/LDS.128)
//   - local softmax stats + partial context from one SMEM pass
// ---------------------------------------------------------------------------
__global__ void __launch_bounds__(256, 3) k_fuse(const float* __restrict__ fm)
{
    extern __shared__ float4 tile4[];       // [c][16] float4, swizzled cols

    __shared__ float  v_s[CC];
    __shared__ float4 sp4[256];             // per-thread score partials
    __shared__ float4 sarr4[PX / 4];
    __shared__ float4 e4s [PX / 4];
    __shared__ float  m_sh, sum_sh;
    float* s_arr = reinterpret_cast<float*>(sarr4);
    float* e_sh  = reinterpret_cast<float*>(e4s);

    const int b   = blockIdx.x;
    const int blk = blockIdx.y;             // 0..NBLK-1
    const int t   = threadIdx.x;            // 256
    const int pj  = t & 15;                 // this thread's pixel float4-group
    const int ch0 = t >> 4;                 // = (c & 15) for all its channels

    v_s[t] = g_v[b * CC + t];
    __syncthreads();

    const float4* fm4 = reinterpret_cast<const float4*>(fm + (size_t)b * CC * HWN);
    const int p4base  = blk * (PX / 4);
    const int swz     = pj ^ ch0;           // swizzled column (constant per thread)

    // ---- load tile + accumulate score partials in registers ----
    float4 part = make_float4(0.f, 0.f, 0.f, 0.f);
#pragma unroll
    for (int ii = 0; ii < 4; ++ii) {
        float4 f[4];
        const int cbase = ch0 + ii * 64;
#pragma unroll
        for (int j = 0; j < 4; ++j)
            f[j] = fm4[(cbase + j * 16) * (HWN / 4) + p4base + pj];
#pragma unroll
        for (int j = 0; j < 4; ++j) {
            const int c = cbase + j * 16;
            tile4[c * 16 + swz] = f[j];
            const float vc = v_s[c];
            part.x += f[j].x * vc; part.y += f[j].y * vc;
            part.z += f[j].z * vc; part.w += f[j].w * vc;
        }
    }
    sp4[t] = part;
    __syncthreads();

    // ---- reduce 16 channel-partials per pixel-group -> scores ----
    if (t < 16) {
        float4 s = sp4[t];
#pragma unroll
        for (int u = 1; u < 16; ++u) {
            float4 x = sp4[t + u * 16];
            s.x += x.x; s.y += x.y; s.z += x.z; s.w += x.w;
        }
        sarr4[t] = s;
    }
    __syncthreads();

    // ---- local max over 64 scores ----
    if (t < 32) {
        float m = fmaxf(s_arr[t], s_arr[t + 32]);
#pragma unroll
        for (int o = 16; o; o >>= 1) m = fmaxf(m, __shfl_xor_sync(0xffffffffu, m, o));
        if (t == 0) m_sh = m;
    }
    __syncthreads();
    const float M = m_sh;

    if (t < PX) e_sh[t] = expf(s_arr[t] - M);
    __syncthreads();

    if (t < 32) {
        float s = e_sh[t] + e_sh[t + 32];
#pragma unroll
        for (int o = 16; o; o >>= 1) s += __shfl_xor_sync(0xffffffffu, s, o);
        if (t == 0) sum_sh = s;
    }
    __syncthreads();

    if (t == 0) {
        g_pm[b * NBLK + blk] = M;
        g_ps[b * NBLK + blk] = sum_sh;
    }

    // ---- partial ctx: thread t = channel; swizzled LDS.128, e4 broadcast ----
    {
        const int csw = t & 15;
        float acc = 0.f;
#pragma unroll
        for (int j = 0; j < 16; ++j) {
            float4 fv = tile4[t * 16 + (j ^ csw)];
            float4 ev = e4s[j];
            acc += fv.x * ev.x + fv.y * ev.y + fv.z * ev.z + fv.w * ev.w;
        }
        g_pctx[(b * NBLK + blk) * CC + t] = acc;
    }
}

// ---------------------------------------------------------------------------
// Kernel 4: combine partials with exact softmax rescaling. grid (B, 8).
// Per-b stats recomputed redundantly (64 floats, L2-hit); pctx reads coalesced.
// ---------------------------------------------------------------------------
__global__ void k_combine(float* __restrict__ out)
{
    const int b  = blockIdx.x;
    const int c0 = blockIdx.y * 32;
    const int t  = threadIdx.x;            // 256

    __shared__ float w_s[NBLK];
    __shared__ float red[8][32];
    __shared__ float M_sh, d_sh;

    if (t < NBLK) w_s[t] = g_pm[b * NBLK + t];
    __syncthreads();

    if (t < 32) {
        float m = fmaxf(w_s[t], w_s[t + 32]);
#pragma unroll
        for (int o = 16; o; o >>= 1) m = fmaxf(m, __shfl_xor_sync(0xffffffffu, m, o));
        if (t == 0) M_sh = m;
    }
    __syncthreads();
    const float M = M_sh;

    if (t < NBLK) w_s[t] = expf(w_s[t] - M);
    __syncthreads();

    if (t < 32) {
        float d = g_ps[b * NBLK + t]      * w_s[t]
                + g_ps[b * NBLK + t + 32] * w_s[t + 32];
#pragma unroll
        for (int o = 16; o; o >>= 1) d += __shfl_xor_sync(0xffffffffu, d, o);
        if (t == 0) d_sh = d;
    }
    __syncthreads();
    const float inv = 1.f / d_sh;

    const int cl = t & 31, prt = t >> 5;   // 8 block-partitions x 32 channels
    float acc = 0.f;
#pragma unroll
    for (int u = 0; u < 8; ++u) {
        const int blk = prt * 8 + u;
        acc += g_pctx[(b * NBLK + blk) * CC + c0 + cl] * w_s[blk];
    }
    red[prt][cl] = acc;
    __syncthreads();
    if (t < 32) {
        float s = 0.f;
#pragma unroll
        for (int u = 0; u < 8; ++u) s += red[u][t];
        out[b * CC + c0 + t] = s * inv;
    }
}

// ---------------------------------------------------------------------------
// Launch
// ---------------------------------------------------------------------------
extern "C" void kernel_launch(void* const* d_in, const int* in_sizes, int n_in,
                              void* d_out, int out_size)
{
    const float* h_dec = nullptr;
    const float* fm    = nullptr;
    const float* W_fm  = nullptr;
    const float* W_h   = nullptr;
    const float* b_h   = nullptr;
    const float* biases[2] = {nullptr, nullptr};
    int nb = 0;

    for (int i = 0; i < n_in; ++i) {
        switch (in_sizes[i]) {
            case BB * HSZ:      h_dec = (const float*)d_in[i]; break;   // 16384
            case BB * CC * HWN: fm    = (const float*)d_in[i]; break;   // 33554432
            case CC * AA:       W_fm  = (const float*)d_in[i]; break;   // 65536
            case HSZ * AA:      W_h   = (const float*)d_in[i]; break;   // 131072
            case AA:            if (nb < 2) biases[nb++] = (const float*)d_in[i]; break;
            default: break;
        }
    }
    b_h = biases[1];   // metadata order: b_fm first (unused), b_h second

    float* out = (float*)d_out;

    const int smem_bytes = CC * 16 * sizeof(float4);   // 65536
    // Idempotent, deterministic, not a stream op (no static guard per harness rules).
    cudaFuncSetAttribute(k_fuse, cudaFuncAttributeMaxDynamicSharedMemorySize,
                         smem_bytes);

    k_wh     <<<dim3(4, 8),   256>>>(h_dec, W_h);
    k_v      <<<dim3(BB, CC / 8), 256>>>(W_fm, b_h);
    k_fuse   <<<dim3(BB, NBLK), 256, smem_bytes>>>(fm);
    k_combine<<<dim3(BB, 8),  256>>>(out);
}

// round 6
// speedup vs baseline: 1.6041x; 1.3193x over previous
#include <cuda_runtime.h>
#include <cstddef>

// Problem constants (Attention_88811333746876)
#define BB   32
#define HSZ  512
#define CC   256
#define HWN  4096     // 64*64
#define AA   256

#define PX    64          // pixels per tile
#define NBLK  (HWN / PX)  // 64 tiles per batch
#define TILES (BB * NBLK) // 2048
#define GRIDP 296         // persistent grid: 2 CTAs x 148 SMs

// Scratch (allocation-free rule: __device__ globals)
__device__ float g_whp[8 * BB * AA];         // k-split partials of wh
__device__ float g_v  [BB * CC];
__device__ float g_pctx[TILES * CC];         // 2 MB partial contexts
__device__ float g_pm[TILES];                // per-tile local max
__device__ float g_ps[TILES];                // per-tile local exp-sum

// ---------------------------------------------------------------------------
// Kernel 1: wh partials. grid (4 a-tiles, 8 k-tiles), 256 thr.
// W_h read exactly once (512 KB, coalesced float4).
// ---------------------------------------------------------------------------
__global__ void k_wh(const float* __restrict__ h_dec,
                     const float* __restrict__ W_h)
{
    __shared__ float Wt[64 * 64];   // [k][a]
    __shared__ float hs[BB * 64];   // [b][k]

    const int a0 = blockIdx.x * 64;
    const int k0 = blockIdx.y * 64;
    const int kp = blockIdx.y;
    const int t  = threadIdx.x;

    {
        const float4* W4 = reinterpret_cast<const float4*>(W_h);
        const int a4 = t & 15, kk = t >> 4;
#pragma unroll
        for (int ii = 0; ii < 4; ++ii) {
            const int k = kk + ii * 16;
            float4 w = W4[(size_t)(k0 + k) * (AA / 4) + (a0 >> 2) + a4];
            reinterpret_cast<float4*>(Wt)[k * 16 + a4] = w;
        }
    }
    {
        const int k = t & 63, bq = t >> 6;
#pragma unroll
        for (int jj = 0; jj < 8; ++jj) {
            const int b = bq + jj * 4;
            hs[b * 64 + k] = h_dec[b * HSZ + k0 + k];
        }
    }
    __syncthreads();

    const int ap2 = t & 31;
    const int bq  = t >> 5;
    float acc[4][2] = {};
#pragma unroll 4
    for (int k = 0; k < 64; ++k) {
        const float w0 = Wt[k * 64 + ap2];
        const float w1 = Wt[k * 64 + ap2 + 32];
#pragma unroll
        for (int i = 0; i < 4; ++i) {
            const float h = hs[(bq * 4 + i) * 64 + k];
            acc[i][0] += h * w0;
            acc[i][1] += h * w1;
        }
    }
#pragma unroll
    for (int i = 0; i < 4; ++i) {
        const int b = bq * 4 + i;
        g_whp[(kp * BB + b) * AA + a0 + ap2]      = acc[i][0];
        g_whp[(kp * BB + b) * AA + a0 + ap2 + 32] = acc[i][1];
    }
}

// ---------------------------------------------------------------------------
// Kernel 2: v[b,c] = sum_a W_fm[c,a] * (sum_kp whp + b_h)[a]
// (b_fm dropped: per-b constant shift -> softmax invariant)
// ---------------------------------------------------------------------------
__global__ void k_v(const float* __restrict__ W_fm,
                    const float* __restrict__ b_h)
{
    const int b    = blockIdx.x;
    const int c    = blockIdx.y * 8 + (threadIdx.x >> 5);
    const int lane = threadIdx.x & 31;

    __shared__ float wh_s[AA];
    if (threadIdx.x < AA) {
        float s = b_h[threadIdx.x];
#pragma unroll
        for (int kp = 0; kp < 8; ++kp)
            s += g_whp[(kp * BB + b) * AA + threadIdx.x];
        wh_s[threadIdx.x] = s;
    }
    __syncthreads();

    const float4* wrow = reinterpret_cast<const float4*>(W_fm + c * AA);
    const float4* whs4 = reinterpret_cast<const float4*>(wh_s);

    float acc = 0.f;
#pragma unroll
    for (int i = 0; i < 2; ++i) {
        const int idx = lane + i * 32;
        float4 wv = wrow[idx];
        float4 hv = whs4[idx];
        acc += wv.x * hv.x + wv.y * hv.y + wv.z * hv.z + wv.w * hv.w;
    }
#pragma unroll
    for (int o = 16; o; o >>= 1) acc += __shfl_xor_sync(0xffffffffu, acc, o);
    if (lane == 0) g_v[b * CC + c] = acc;
}

// ---------------------------------------------------------------------------
// Kernel 3: persistent fused pass. Tile [256c x 64px] held in REGISTERS
// (16 float4/thread) -- no SMEM staging of fm. Per tile:
//   LDG+score-FMA -> shfl+smem score reduce -> local max/exp/sum ->
//   ctx partial dots from registers -> stride-17 smem transpose -> STG.
// l1tex traffic ~2x lower than the SMEM-tile version; DRAM is sole binder.
// ---------------------------------------------------------------------------
__global__ void __launch_bounds__(256, 2) k_fuse(const float* __restrict__ fm)
{
    __shared__ float4 sp4[8 * 16];       // per-warp score partials (2 KB)
    __shared__ float4 sarr4[PX / 4];
    __shared__ float4 e4s [PX / 4];
    __shared__ float  m_sh;
    __shared__ float  ctxp[CC * 17];     // stride-17: conflict-free STS & LDS
    float* s_arr = reinterpret_cast<float*>(sarr4);
    float* e_sh  = reinterpret_cast<float*>(e4s);

    const int t    = threadIdx.x;        // 256
    const int pj   = t & 15;             // pixel float4-group (coalescing key)
    const int ch0  = t >> 4;             // channel residue mod 16
    const int wid  = t >> 5;
    const int lane = t & 31;

    for (int idx = blockIdx.x; idx < TILES; idx += gridDim.x) {
        const int b   = idx >> 6;
        const int blk = idx & 63;
        const float4* fm4 = reinterpret_cast<const float4*>(fm + (size_t)b * CC * HWN);
        const int p4 = blk * (PX / 4) + pj;

        // ---- load 16 channel-rows into registers (MLP 16, no barrier above) ----
        float4 f[16];
#pragma unroll
        for (int u = 0; u < 16; ++u)
            f[u] = fm4[(ch0 + u * 16) * (HWN / 4) + p4];

        // ---- score partial from registers; v from L2 (1 KB, hot) ----
        float4 part = make_float4(0.f, 0.f, 0.f, 0.f);
#pragma unroll
        for (int u = 0; u < 16; ++u) {
            const float vc = __ldg(&g_v[b * CC + ch0 + u * 16]);
            part.x += f[u].x * vc; part.y += f[u].y * vc;
            part.z += f[u].z * vc; part.w += f[u].w * vc;
        }
        // lanes L and L+16 share pj -> pair-reduce in warp
        part.x += __shfl_xor_sync(0xffffffffu, part.x, 16);
        part.y += __shfl_xor_sync(0xffffffffu, part.y, 16);
        part.z += __shfl_xor_sync(0xffffffffu, part.z, 16);
        part.w += __shfl_xor_sync(0xffffffffu, part.w, 16);

        if (lane < 16) sp4[wid * 16 + pj] = part;
        __syncthreads();                               // B

        if (t < 16) {
            float4 s = sp4[t];
#pragma unroll
            for (int w = 1; w < 8; ++w) {
                float4 x = sp4[w * 16 + t];
                s.x += x.x; s.y += x.y; s.z += x.z; s.w += x.w;
            }
            sarr4[t] = s;
        }
        __syncthreads();                               // C

        if (t < 32) {
            float m = fmaxf(s_arr[t], s_arr[t + 32]);
#pragma unroll
            for (int o = 16; o; o >>= 1)
                m = fmaxf(m, __shfl_xor_sync(0xffffffffu, m, o));
            if (t == 0) m_sh = m;
        }
        __syncthreads();                               // D
        const float M = m_sh;

        if (t < PX) e_sh[t] = expf(s_arr[t] - M);
        __syncthreads();                               // E

        const float4 e4 = e4s[pj];

        if (t < 32) {
            float s = e_sh[t] + e_sh[t + 32];
#pragma unroll
            for (int o = 16; o; o >>= 1)
                s += __shfl_xor_sync(0xffffffffu, s, o);
            if (t == 0) { g_pm[idx] = M; g_ps[idx] = s; }
        }

        // ---- ctx partials straight from registers ----
#pragma unroll
        for (int u = 0; u < 16; ++u) {
            const float d = f[u].x * e4.x + f[u].y * e4.y
                          + f[u].z * e4.z + f[u].w * e4.w;
            ctxp[(ch0 + u * 16) * 17 + pj] = d;
        }
        __syncthreads();                               // F

        {
            float acc = 0.f;
#pragma unroll
            for (int q = 0; q < 16; ++q) acc += ctxp[t * 17 + q];
            g_pctx[(size_t)idx * CC + t] = acc;        // coalesced 1 KB
        }
        __syncthreads();                               // protect sp4 vs gather
    }
}

// ---------------------------------------------------------------------------
// Kernel 4: exact softmax rescale + combine. grid (B, 8), 512 thr
// (16 partitions x 32 channels; 4 blk-reads per thread; 2 MB L2-hot).
// ---------------------------------------------------------------------------
__global__ void k_combine(float* __restrict__ out)
{
    const int b  = blockIdx.x;
    const int c0 = blockIdx.y * 32;
    const int t  = threadIdx.x;            // 512
    const int cl = t & 31, prt = t >> 5;   // 16 partitions

    __shared__ float w_s[NBLK];
    __shared__ float red[16][32];
    __shared__ float M_sh, d_sh;

    if (t < NBLK) w_s[t] = g_pm[b * NBLK + t];
    __syncthreads();

    if (t < 32) {
        float m = fmaxf(w_s[t], w_s[t + 32]);
#pragma unroll
        for (int o = 16; o; o >>= 1) m = fmaxf(m, __shfl_xor_sync(0xffffffffu, m, o));
        if (t == 0) M_sh = m;
    }
    __syncthreads();
    const float M = M_sh;

    if (t < NBLK) w_s[t] = expf(w_s[t] - M);
    __syncthreads();

    if (t < 32) {
        float d = g_ps[b * NBLK + t]      * w_s[t]
                + g_ps[b * NBLK + t + 32] * w_s[t + 32];
#pragma unroll
        for (int o = 16; o; o >>= 1) d += __shfl_xor_sync(0xffffffffu, d, o);
        if (t == 0) d_sh = d;
    }
    __syncthreads();
    const float inv = 1.f / d_sh;

    float acc = 0.f;
#pragma unroll
    for (int u = 0; u < 4; ++u) {
        const int blk = prt * 4 + u;
        acc += g_pctx[(size_t)(b * NBLK + blk) * CC + c0 + cl] * w_s[blk];
    }
    red[prt][cl] = acc;
    __syncthreads();
    if (t < 32) {
        float s = 0.f;
#pragma unroll
        for (int u = 0; u < 16; ++u) s += red[u][t];
        out[b * CC + c0 + t] = s * inv;
    }
}

// ---------------------------------------------------------------------------
// Launch
// ---------------------------------------------------------------------------
extern "C" void kernel_launch(void* const* d_in, const int* in_sizes, int n_in,
                              void* d_out, int out_size)
{
    const float* h_dec = nullptr;
    const float* fm    = nullptr;
    const float* W_fm  = nullptr;
    const float* W_h   = nullptr;
    const float* b_h   = nullptr;
    const float* biases[2] = {nullptr, nullptr};
    int nb = 0;

    for (int i = 0; i < n_in; ++i) {
        switch (in_sizes[i]) {
            case BB * HSZ:      h_dec = (const float*)d_in[i]; break;   // 16384
            case BB * CC * HWN: fm    = (const float*)d_in[i]; break;   // 33554432
            case CC * AA:       W_fm  = (const float*)d_in[i]; break;   // 65536
            case HSZ * AA:      W_h   = (const float*)d_in[i]; break;   // 131072
            case AA:            if (nb < 2) biases[nb++] = (const float*)d_in[i]; break;
            default: break;
        }
    }
    b_h = biases[1];   // metadata order: b_fm first (unused), b_h second

    float* out = (float*)d_out;

    k_wh     <<<dim3(4, 8),       256>>>(h_dec, W_h);
    k_v      <<<dim3(BB, CC / 8), 256>>>(W_fm, b_h);
    k_fuse   <<<GRIDP,            256>>>(fm);
    k_combine<<<dim3(BB, 8),      512>>>(out);
}